// round 9
// baseline (speedup 1.0000x reference)
#include <cuda_runtime.h>
#include <math.h>

#define B_SZ    8
#define T_LEN   4096
#define D_INP   128
#define D_OUTP  128
#define N_ST    256
#define CHUNKS  128                  /* 32-step scan chunks */
#define TT      64                   /* k1 time-tile */
#define NBLK1   (B_SZ * T_LEN / TT)  /* 512 */
#define TT2     128                  /* k2 time-tile */
#define NBLK2   (B_SZ * T_LEN / TT2) /* 256 */
#define N_ROWS  320                  /* 256 state rows + 64 x-pair rows */

typedef unsigned long long u64;

// q-permutation for 4-wide n-groups: column q holds channel n(q)
// q = w*16 + i*4 + ngl  <->  n = w*16 + ngl*4 + i
__host__ __device__ __forceinline__ int qperm(int q) {
    return (q & ~15) | ((q & 3) << 2) | ((q >> 2) & 3);
}

// ---------------- scratch ----------------
__device__ u64    g_Bsw [128 * 64 * 6];         // [k][ng(64)][6]: n=ng*4+r (r<4), pad r=4,5
__device__ u64    g_CDsw[N_ROWS * 16 * 10];     // [q][dg(16)][10]: C rows (q-permuted) / folded-D rows
__device__ float2 g_lam [N_ST];
__device__ float2 g_lamL[N_ST];                 // lambda^32
__device__ float2 g_states[(size_t)B_SZ * T_LEN * N_ST];   // [t][q]
__device__ float2 g_carry[B_SZ * CHUNKS * N_ST];
__device__ float2 g_pref [B_SZ * CHUNKS * N_ST];

// ---------------- helpers ----------------
__device__ __forceinline__ u64 pk2(float lo, float hi) {
    u64 r; asm("mov.b64 %0, {%1, %2};" : "=l"(r) : "f"(lo), "f"(hi)); return r;
}
__device__ __forceinline__ void upk2(u64 v, float& lo, float& hi) {
    asm("mov.b64 {%0, %1}, %2;" : "=f"(lo), "=f"(hi) : "l"(v));
}
__device__ __forceinline__ u64 fma2(u64 a, u64 b, u64 c) {
    u64 d; asm("fma.rn.f32x2 %0, %1, %2, %3;" : "=l"(d) : "l"(a), "l"(b), "l"(c)); return d;
}
__device__ __forceinline__ float2 cmul(float2 a, float2 b) {
    return make_float2(a.x * b.x - a.y * b.y, a.x * b.y + a.y * b.x);
}

// ---------------- kernel 0: parameter prep ----------------
__global__ void lru_prep(const float* __restrict__ nu_log,
                         const float* __restrict__ theta_log,
                         const float* __restrict__ gamma_log,
                         const float* __restrict__ B_re, const float* __restrict__ B_im,
                         const float* __restrict__ C_re, const float* __restrict__ C_im,
                         const float* __restrict__ Dm) {
    int idx = blockIdx.x * blockDim.x + threadIdx.x;   // grid covers 51200
    if (idx < N_ST) {
        float la = expf(-expf(nu_log[idx]));
        float ph = expf(theta_log[idx]);
        float2 lam = make_float2(la * cosf(ph), la * sinf(ph));
        g_lam[idx] = lam;
        float2 p = lam;
        #pragma unroll
        for (int i = 0; i < 5; i++) p = cmul(p, p);     // lam^32
        g_lamL[idx] = p;
    }
    if (idx < 128 * 64 * 6) {          // g_Bsw (stride 6: 16B-aligned ull2 rows)
        int r  = idx % 6;
        int ng = (idx / 6) % 64;
        int k  = idx / 384;
        u64 v = 0ULL;
        if (r < 4) {
            int n = ng * 4 + r;
            float g = expf(gamma_log[n]);
            v = pk2(g * B_re[n * D_INP + k], g * B_im[n * D_INP + k]);
        }
        g_Bsw[idx] = v;
    }
    if (idx < N_ROWS * 16 * 10) {      // g_CDsw (q-permuted state rows + folded D)
        int r  = idx % 10;
        int dg = (idx / 10) % 16;
        int R  = idx / 160;
        u64 v = 0ULL;
        if (r < 8) {
            int d = dg * 8 + r;
            if (R < N_ST) {
                int n = qperm(R);
                v = pk2(C_re[d * N_ST + n], C_im[d * N_ST + n]);
            } else {
                int kp = R - N_ST;
                v = pk2(Dm[d * D_INP + 2 * kp], -Dm[d * D_INP + 2 * kp + 1]);
            }
        }
        g_CDsw[idx] = v;
    }
}

// ---------------- kernel 1: Bu = x @ BcT + chunk-local scan ----------------
// smem: bsw u64[16*64*6] = 49152B | xs u64[128][66] = 67584B  -> 116736B
#define K1_SMEM (16 * 64 * 6 * 8 + 128 * 66 * 8)

__global__ __launch_bounds__(512, 1) void lru_bu_scan(const float* __restrict__ x) {
    extern __shared__ char smem[];
    u64* bsw = (u64*)smem;
    u64* xs  = (u64*)(smem + 16 * 64 * 6 * 8);     // [k][sigma(t)] duplicated pairs

    int b   = blockIdx.x >> 6;
    int c2  = blockIdx.x & 63;
    int tid = threadIdx.x;
    int lane = tid & 31, w = tid >> 5;   // w 0..15
    int ngl = lane & 3, tg = lane >> 2;  // tg 0..7
    int ng  = w * 4 + ngl;               // 0..63, n = ng*4 + i
    size_t tbase = (size_t)b * T_LEN + c2 * TT;

    // ---- stage x: xs[k][sigma(t)] = (v,v), sigma(t) = (t>>3) | ((t&7)<<3) ----
    {
        int k = tid & 127, tq = tid >> 7;           // tq 0..3, 16 t's each
        const float* xp = x + tbase * D_INP + k;
        #pragma unroll
        for (int i = 0; i < 16; i++) {
            int t = tq * 16 + i;
            float v = xp[(size_t)t * D_INP];
            xs[k * 66 + ((t >> 3) | ((t & 7) << 3))] = pk2(v, v);
        }
    }

    u64 acc[32];                         // [i(4 n)][j(8 t)]
    #pragma unroll
    for (int i = 0; i < 32; i++) acc[i] = 0ULL;

    for (int kt = 0; kt < 8; kt++) {
        __syncthreads();
        const float4* src = (const float4*)(g_Bsw + kt * 6144);
        float4* dst = (float4*)bsw;
        #pragma unroll
        for (int i = 0; i < 6; i++) dst[tid + i * 512] = src[tid + i * 512];
        __syncthreads();
        #pragma unroll 4
        for (int kk = 0; kk < 16; kk++) {
            const ulonglong2* bp = (const ulonglong2*)(bsw + (kk * 64 + ng) * 6);
            ulonglong2 b01 = bp[0], b23 = bp[1];
            const u64* xr = xs + (kt * 16 + kk) * 66 + tg;
            u64 xd[8];
            #pragma unroll
            for (int j = 0; j < 8; j++) xd[j] = xr[j * 8];
            u64 bv[4] = {b01.x, b01.y, b23.x, b23.y};
            #pragma unroll
            for (int i = 0; i < 4; i++)
                #pragma unroll
                for (int j = 0; j < 8; j++)
                    acc[i * 8 + j] = fma2(xd[j], bv[i], acc[i * 8 + j]);
        }
    }

    // ---- chunk-local scan via warp shuffles ----
    int tgm = tg & 3;                 // position within 32-chunk
    int cc  = tg >> 2;                // which chunk of the two
    int cblk = b * CHUNKS + c2 * 2 + cc;

    #pragma unroll
    for (int i = 0; i < 4; i++) {
        int n = ng * 4 + i;
        float2 lam = g_lam[n];
        float2 l2 = cmul(lam, lam), l4 = cmul(l2, l2);
        float2 l8 = cmul(l4, l4),  l16 = cmul(l8, l8);

        float sr[8], si[8];
        float cr = 0.f, ci = 0.f;
        #pragma unroll
        for (int j = 0; j < 8; j++) {
            float br, bi; upk2(acc[i * 8 + j], br, bi);
            float nr = fmaf(lam.x, cr, fmaf(-lam.y, ci, br));
            float ni = fmaf(lam.x, ci, fmaf( lam.y, cr, bi));
            cr = nr; ci = ni; sr[j] = nr; si[j] = ni;
        }
        float vr = sr[7], vi = si[7];
        float tr = __shfl_up_sync(0xffffffffu, vr, 4);
        float ti = __shfl_up_sync(0xffffffffu, vi, 4);
        if (tgm >= 1) {
            vr = fmaf(l8.x, tr, fmaf(-l8.y, ti, vr));
            vi = fmaf(l8.x, ti, fmaf( l8.y, tr, vi));
        }
        tr = __shfl_up_sync(0xffffffffu, vr, 8);
        ti = __shfl_up_sync(0xffffffffu, vi, 8);
        if (tgm >= 2) {
            vr = fmaf(l16.x, tr, fmaf(-l16.y, ti, vr));
            vi = fmaf(l16.x, ti, fmaf( l16.y, tr, vi));
        }
        float Cr = __shfl_up_sync(0xffffffffu, vr, 4);
        float Ci = __shfl_up_sync(0xffffffffu, vi, 4);
        if (tgm == 0) { Cr = 0.f; Ci = 0.f; }

        float pwr = lam.x, pwi = lam.y;
        // states column q = w*16 + i*4 + ngl
        float2* sp = g_states + (tbase + tg * 8) * N_ST + (w * 16 + i * 4 + ngl);
        #pragma unroll
        for (int j = 0; j < 8; j++) {
            float rr = fmaf(pwr, Cr, fmaf(-pwi, Ci, sr[j]));
            float ri = fmaf(pwr, Ci, fmaf( pwi, Cr, si[j]));
            sp[j * N_ST] = make_float2(rr, ri);
            if (j == 7 && tgm == 3) g_carry[cblk * N_ST + n] = make_float2(rr, ri);
            float npr = fmaf(pwr, lam.x, -pwi * lam.y);
            float npi = fmaf(pwr, lam.y,  pwi * lam.x);
            pwr = npr; pwi = npi;
        }
    }
}

// ---------------- kernel 1b: exclusive prefix over chunk carries ----------------
__global__ void lru_prefix() {
    int b = blockIdx.x;            // 8
    int n = threadIdx.x;           // 256
    float2 lamL = g_lamL[n];
    float2 pre = make_float2(0.f, 0.f);
    const float2* cp = g_carry + b * CHUNKS * N_ST + n;
    float2*       pp = g_pref  + b * CHUNKS * N_ST + n;
    #pragma unroll 1
    for (int cb = 0; cb < CHUNKS; cb += 16) {
        float2 cj[16];
        #pragma unroll
        for (int u = 0; u < 16; u++) cj[u] = cp[(cb + u) * N_ST];
        #pragma unroll
        for (int u = 0; u < 16; u++) {
            pp[(cb + u) * N_ST] = pre;
            pre = cmul(lamL, pre);
            pre.x += cj[u].x; pre.y += cj[u].y;
        }
    }
}

// ---------------- kernel 2: correction + y = Re(states @ C^T) + x @ D^T ----------------
// smem: stT u64[32][130] = 33280B | ct u64[32*16*10] = 40960B  -> 74240B
#define K2_SMEM (32 * 130 * 8 + 32 * 16 * 10 * 8)

__global__ __launch_bounds__(512, 1) void lru_fix_out(const float* __restrict__ x,
                                                      float* __restrict__ y) {
    extern __shared__ char smem[];
    u64* stT = (u64*)smem;                        // [row][sigma2(t)], sigma2 = (t>>2)|((t&3)<<5)
    u64* ct  = (u64*)(smem + 32 * 130 * 8);

    int b   = blockIdx.x >> 5;
    int c2  = blockIdx.x & 31;
    int tid = threadIdx.x;
    int lane = tid & 31, w = tid >> 5;            // w 0..15
    int dgl = lane & 3, tgl = lane >> 2;          // tgl 0..7
    int dg  = (w & 3) * 4 + dgl;                  // 0..15, d = dg*8
    int tg  = (w >> 2) * 8 + tgl;                 // 0..31, t = tg*4 + j
    size_t tbase = (size_t)b * T_LEN + c2 * TT2;
    int row = tid & 31, tseg = tid >> 5;          // phase-A: 32 rows x 16 tsegs of 8 t

    u64 acc[32];                                  // [i(8 d)][j(4 t)]
    #pragma unroll
    for (int i = 0; i < 32; i++) acc[i] = 0ULL;

    for (int nt = 0; nt < 10; nt++) {
        __syncthreads();
        // ---- load ct tile ----
        {
            const float4* src = (const float4*)(g_CDsw + nt * 5120);
            float4* dst = (float4*)ct;
            #pragma unroll
            for (int i = 0; i < 5; i++) dst[tid + i * 512] = src[tid + i * 512];
        }
        // ---- phase A: build stT tile (32 rows x 128 t) ----
        {
            int q = nt * 32 + row;
            int t0 = tseg * 8;
            if (q < N_ST) {
                int n = qperm(q);
                float2 lam = g_lam[n];
                float2 l2 = cmul(lam, lam), l4 = cmul(l2, l2);
                float2 l8c = cmul(l4, l4), l16 = cmul(l8c, l8c);
                float2 pre = g_pref[(b * CHUNKS + c2 * 4 + (tseg >> 2)) * N_ST + n];
                float2 pw = lam;
                if (tseg & 1) pw = cmul(pw, l8c);
                if (tseg & 2) pw = cmul(pw, l16);
                const float2* sp = g_states + (tbase + t0) * N_ST + q;
                #pragma unroll
                for (int i = 0; i < 8; i++) {
                    float2 lv = sp[i * N_ST];
                    float rr = fmaf(pw.x, pre.x, fmaf(-pw.y, pre.y, lv.x));
                    float ri = fmaf(pw.x, pre.y, fmaf( pw.y, pre.x, lv.y));
                    int t = t0 + i;
                    stT[row * 130 + ((t >> 2) | ((t & 3) << 5))] = pk2(rr, ri);
                    float npr = fmaf(pw.x, lam.x, -pw.y * lam.y);
                    float npi = fmaf(pw.x, lam.y,  pw.y * lam.x);
                    pw.x = npr; pw.y = npi;
                }
            } else {
                int kp = q - N_ST;
                const float* xp = x + (tbase + t0) * D_INP + 2 * kp;
                #pragma unroll
                for (int i = 0; i < 8; i++) {
                    int t = t0 + i;
                    stT[row * 130 + ((t >> 2) | ((t & 3) << 5))] =
                        *(const u64*)(xp + (size_t)i * D_INP);
                }
            }
        }
        __syncthreads();
        // ---- phase B: GEMM over this 32-row tile ----
        #pragma unroll 4
        for (int kk = 0; kk < 32; kk++) {
            const ulonglong2* cp2 = (const ulonglong2*)(ct + (kk * 16 + dg) * 10);
            ulonglong2 c01 = cp2[0], c23 = cp2[1], c45 = cp2[2], c67 = cp2[3];
            const u64* sr = stT + kk * 130 + tg;
            u64 sv[4];
            #pragma unroll
            for (int j = 0; j < 4; j++) sv[j] = sr[j * 32];
            u64 cv[8] = {c01.x, c01.y, c23.x, c23.y, c45.x, c45.y, c67.x, c67.y};
            #pragma unroll
            for (int i = 0; i < 8; i++)
                #pragma unroll
                for (int j = 0; j < 4; j++)
                    acc[i * 4 + j] = fma2(sv[j], cv[i], acc[i * 4 + j]);
        }
    }

    // ---- epilogue: Re() = lo - hi (D-term folded via sign trick) ----
    float* yp = y + (tbase + tg * 4) * D_OUTP + dg * 8;
    #pragma unroll
    for (int j = 0; j < 4; j++) {
        float r[8];
        #pragma unroll
        for (int i = 0; i < 8; i++) {
            float a, bb; upk2(acc[i * 4 + j], a, bb);
            r[i] = a - bb;
        }
        *(float4*)(yp + (size_t)j * D_OUTP)     = make_float4(r[0], r[1], r[2], r[3]);
        *(float4*)(yp + (size_t)j * D_OUTP + 4) = make_float4(r[4], r[5], r[6], r[7]);
    }
}

// ---------------- launch ----------------
extern "C" void kernel_launch(void* const* d_in, const int* in_sizes, int n_in,
                              void* d_out, int out_size) {
    (void)in_sizes; (void)n_in; (void)out_size;
    const float* x         = (const float*)d_in[0];
    const float* nu_log    = (const float*)d_in[1];
    const float* theta_log = (const float*)d_in[2];
    const float* gamma_log = (const float*)d_in[3];
    const float* B_re      = (const float*)d_in[4];
    const float* B_im      = (const float*)d_in[5];
    const float* C_re      = (const float*)d_in[6];
    const float* C_im      = (const float*)d_in[7];
    const float* Dm        = (const float*)d_in[8];
    float* y = (float*)d_out;

    cudaFuncSetAttribute(lru_bu_scan, cudaFuncAttributeMaxDynamicSharedMemorySize, K1_SMEM);
    cudaFuncSetAttribute(lru_fix_out, cudaFuncAttributeMaxDynamicSharedMemorySize, K2_SMEM);

    lru_prep<<<200, 256>>>(nu_log, theta_log, gamma_log, B_re, B_im, C_re, C_im, Dm);
    lru_bu_scan<<<NBLK1, 512, K1_SMEM>>>(x);
    lru_prefix<<<B_SZ, N_ST>>>();
    lru_fix_out<<<NBLK2, 512, K2_SMEM>>>(x, y);
}

// round 12
// speedup vs baseline: 1.3657x; 1.3657x over previous
#include <cuda_runtime.h>
#include <cuda_bf16.h>
#include <math.h>

#define B_SZ    8
#define T_LEN   4096
#define D_INP   128
#define D_OUTP  128
#define N_ST    256
#define CHUNKS  128                  /* 32-step scan chunks */
#define TT      64                   /* k1 time-tile */
#define NBLK1   (B_SZ * T_LEN / TT)  /* 512 */
#define TT2     128                  /* k2 time-tile */
#define NBLK2   (B_SZ * T_LEN / TT2) /* 256 */

typedef unsigned long long u64;
typedef unsigned int u32;

// column-permutation (involution): state column q holds channel n = qperm(q)
__host__ __device__ __forceinline__ int qperm(int q) {
    return (q & ~15) | ((q & 3) << 2) | ((q >> 2) & 3);
}

// ---------------- scratch ----------------
__device__ u64    g_Bsw [128 * 64 * 6];         // k1 B operand [k][ng(64)][6]
__device__ u32    g_CDh [10 * 4096];            // CD bf16-hi: [kb][d][32 u32]
__device__ u32    g_CDl [10 * 4096];            // CD bf16-lo
__device__ float2 g_lpow[32 * N_ST];            // [tm][q] = lam_{n(q)}^{tm+1}
__device__ float2 g_lam [N_ST];
__device__ float2 g_lamL[N_ST];                 // lambda^32 (n-indexed)
__device__ float2 g_states[(size_t)B_SZ * T_LEN * N_ST];   // [t][q]
__device__ float2 g_carry[B_SZ * CHUNKS * N_ST];           // [chunk][n]
__device__ float2 g_pref [B_SZ * CHUNKS * N_ST];           // [chunk][q]  (q-indexed)

// ---------------- helpers ----------------
__device__ __forceinline__ u64 pk2(float lo, float hi) {
    u64 r; asm("mov.b64 %0, {%1, %2};" : "=l"(r) : "f"(lo), "f"(hi)); return r;
}
__device__ __forceinline__ void upk2(u64 v, float& lo, float& hi) {
    asm("mov.b64 {%0, %1}, %2;" : "=f"(lo), "=f"(hi) : "l"(v));
}
__device__ __forceinline__ u64 fma2(u64 a, u64 b, u64 c) {
    u64 d; asm("fma.rn.f32x2 %0, %1, %2, %3;" : "=l"(d) : "l"(a), "l"(b), "l"(c)); return d;
}
__device__ __forceinline__ float2 cmul(float2 a, float2 b) {
    return make_float2(a.x * b.x - a.y * b.y, a.x * b.y + a.y * b.x);
}
__device__ __forceinline__ u32 pkbf(float lo, float hi) {    // lo -> low half
    u32 r; asm("cvt.rn.bf16x2.f32 %0, %1, %2;" : "=r"(r) : "f"(hi), "f"(lo)); return r;
}
__device__ __forceinline__ float bfround(float v) {
    return __bfloat162float(__float2bfloat16(v));
}
__device__ __forceinline__ u32 smem_u32(const void* p) {
    u32 a; asm("{ .reg .u64 t; cvta.to.shared.u64 t, %1; cvt.u32.u64 %0, t; }" : "=r"(a) : "l"(p));
    return a;
}
__device__ __forceinline__ void ldmx4(u32* r, u32 addr) {
    asm volatile("ldmatrix.sync.aligned.m8n8.x4.shared.b16 {%0,%1,%2,%3}, [%4];"
                 : "=r"(r[0]), "=r"(r[1]), "=r"(r[2]), "=r"(r[3]) : "r"(addr));
}
__device__ __forceinline__ void mma16816(float* d, const u32* a, const u32* b) {
    asm volatile("mma.sync.aligned.m16n8k16.row.col.f32.bf16.bf16.f32 "
                 "{%0,%1,%2,%3}, {%4,%5,%6,%7}, {%8,%9}, {%0,%1,%2,%3};"
                 : "+f"(d[0]), "+f"(d[1]), "+f"(d[2]), "+f"(d[3])
                 : "r"(a[0]), "r"(a[1]), "r"(a[2]), "r"(a[3]), "r"(b[0]), "r"(b[1]));
}

// ---------------- kernel 0: parameter prep ----------------
__global__ void lru_prep(const float* __restrict__ nu_log,
                         const float* __restrict__ theta_log,
                         const float* __restrict__ gamma_log,
                         const float* __restrict__ B_re, const float* __restrict__ B_im,
                         const float* __restrict__ C_re, const float* __restrict__ C_im,
                         const float* __restrict__ Dm) {
    int idx = blockIdx.x * blockDim.x + threadIdx.x;   // grid covers 51200
    if (idx < N_ST) {
        float la = expf(-expf(nu_log[idx]));
        float ph = expf(theta_log[idx]);
        float2 lam = make_float2(la * cosf(ph), la * sinf(ph));
        g_lam[idx] = lam;
        float2 p = lam;
        #pragma unroll
        for (int i = 0; i < 5; i++) p = cmul(p, p);     // lam^32
        g_lamL[idx] = p;
    }
    if (idx < 128 * 64 * 6) {          // g_Bsw for k1
        int r  = idx % 6;
        int ng = (idx / 6) % 64;
        int k  = idx / 384;
        u64 v = 0ULL;
        if (r < 4) {
            int n = ng * 4 + r;
            float g = expf(gamma_log[n]);
            v = pk2(g * B_re[n * D_INP + k], g * B_im[n * D_INP + k]);
        }
        g_Bsw[idx] = v;
    }
    if (idx < 10 * 128 * 32) {         // CD bf16 hi/lo tiles [kb][d][kl]
        int kl = idx % 32;
        int d  = (idx / 32) % 128;
        int kb = idx / 4096;
        float v0, v1;
        if (kb < 8) {
            int q = kb * 32 + kl;
            int n = qperm(q);
            v0 =  C_re[d * N_ST + n];
            v1 = -C_im[d * N_ST + n];
        } else {
            int kk = (kb - 8) * 64 + 2 * kl;
            v0 = Dm[d * D_INP + kk];
            v1 = Dm[d * D_INP + kk + 1];
        }
        float h0 = bfround(v0), h1 = bfround(v1);
        g_CDh[idx] = pkbf(h0, h1);
        g_CDl[idx] = pkbf(v0 - h0, v1 - h1);
    }
    if (idx < 32 * N_ST) {             // lam^(tm+1) table, q-indexed
        int tm = idx >> 8, q = idx & 255;
        int n = qperm(q);
        float p = (float)(tm + 1);
        float mag = expf(-p * expf(nu_log[n]));
        float ang = p * expf(theta_log[n]);
        g_lpow[idx] = make_float2(mag * cosf(ang), mag * sinf(ang));
    }
}

// ---------------- kernel 1: Bu = x @ BcT + chunk-local scan (SIMT) ----------------
#define K1_SMEM (16 * 64 * 6 * 8 + 128 * 66 * 8)

__global__ __launch_bounds__(512, 1) void lru_bu_scan(const float* __restrict__ x) {
    extern __shared__ char smem[];
    u64* bsw = (u64*)smem;
    u64* xs  = (u64*)(smem + 16 * 64 * 6 * 8);

    int b   = blockIdx.x >> 6;
    int c2  = blockIdx.x & 63;
    int tid = threadIdx.x;
    int lane = tid & 31, w = tid >> 5;
    int ngl = lane & 3, tg = lane >> 2;
    int ng  = w * 4 + ngl;
    size_t tbase = (size_t)b * T_LEN + c2 * TT;

    {
        int k = tid & 127, tq = tid >> 7;
        const float* xp = x + tbase * D_INP + k;
        #pragma unroll
        for (int i = 0; i < 16; i++) {
            int t = tq * 16 + i;
            float v = xp[(size_t)t * D_INP];
            xs[k * 66 + ((t >> 3) | ((t & 7) << 3))] = pk2(v, v);
        }
    }

    u64 acc[32];
    #pragma unroll
    for (int i = 0; i < 32; i++) acc[i] = 0ULL;

    for (int kt = 0; kt < 8; kt++) {
        __syncthreads();
        const float4* src = (const float4*)(g_Bsw + kt * 6144);
        float4* dst = (float4*)bsw;
        #pragma unroll
        for (int i = 0; i < 6; i++) dst[tid + i * 512] = src[tid + i * 512];
        __syncthreads();
        #pragma unroll 4
        for (int kk = 0; kk < 16; kk++) {
            const ulonglong2* bp = (const ulonglong2*)(bsw + (kk * 64 + ng) * 6);
            ulonglong2 b01 = bp[0], b23 = bp[1];
            const u64* xr = xs + (kt * 16 + kk) * 66 + tg;
            u64 xd[8];
            #pragma unroll
            for (int j = 0; j < 8; j++) xd[j] = xr[j * 8];
            u64 bv[4] = {b01.x, b01.y, b23.x, b23.y};
            #pragma unroll
            for (int i = 0; i < 4; i++)
                #pragma unroll
                for (int j = 0; j < 8; j++)
                    acc[i * 8 + j] = fma2(xd[j], bv[i], acc[i * 8 + j]);
        }
    }

    int tgm = tg & 3;
    int cc  = tg >> 2;
    int cblk = b * CHUNKS + c2 * 2 + cc;

    #pragma unroll
    for (int i = 0; i < 4; i++) {
        int n = ng * 4 + i;
        float2 lam = g_lam[n];
        float2 l2 = cmul(lam, lam), l4 = cmul(l2, l2);
        float2 l8 = cmul(l4, l4),  l16 = cmul(l8, l8);

        float sr[8], si[8];
        float cr = 0.f, ci = 0.f;
        #pragma unroll
        for (int j = 0; j < 8; j++) {
            float br, bi; upk2(acc[i * 8 + j], br, bi);
            float nr = fmaf(lam.x, cr, fmaf(-lam.y, ci, br));
            float ni = fmaf(lam.x, ci, fmaf( lam.y, cr, bi));
            cr = nr; ci = ni; sr[j] = nr; si[j] = ni;
        }
        float vr = sr[7], vi = si[7];
        float tr = __shfl_up_sync(0xffffffffu, vr, 4);
        float ti = __shfl_up_sync(0xffffffffu, vi, 4);
        if (tgm >= 1) {
            vr = fmaf(l8.x, tr, fmaf(-l8.y, ti, vr));
            vi = fmaf(l8.x, ti, fmaf( l8.y, tr, vi));
        }
        tr = __shfl_up_sync(0xffffffffu, vr, 8);
        ti = __shfl_up_sync(0xffffffffu, vi, 8);
        if (tgm >= 2) {
            vr = fmaf(l16.x, tr, fmaf(-l16.y, ti, vr));
            vi = fmaf(l16.x, ti, fmaf( l16.y, tr, vi));
        }
        float Cr = __shfl_up_sync(0xffffffffu, vr, 4);
        float Ci = __shfl_up_sync(0xffffffffu, vi, 4);
        if (tgm == 0) { Cr = 0.f; Ci = 0.f; }

        float pwr = lam.x, pwi = lam.y;
        float2* sp = g_states + (tbase + tg * 8) * N_ST + (w * 16 + i * 4 + ngl);
        #pragma unroll
        for (int j = 0; j < 8; j++) {
            float rr = fmaf(pwr, Cr, fmaf(-pwi, Ci, sr[j]));
            float ri = fmaf(pwr, Ci, fmaf( pwi, Cr, si[j]));
            sp[j * N_ST] = make_float2(rr, ri);
            if (j == 7 && tgm == 3) g_carry[cblk * N_ST + n] = make_float2(rr, ri);
            float npr = fmaf(pwr, lam.x, -pwi * lam.y);
            float npi = fmaf(pwr, lam.y,  pwi * lam.x);
            pwr = npr; pwi = npi;
        }
    }
}

// ---------------- kernel 1b: exclusive prefix (n-indexed carries -> q-indexed prefix) ----------------
__global__ void lru_prefix() {
    int b = blockIdx.x;            // 8
    int q = threadIdx.x;           // 256
    int n = qperm(q);
    float2 lamL = g_lamL[n];
    float2 pre = make_float2(0.f, 0.f);
    const float2* cp = g_carry + b * CHUNKS * N_ST + n;
    float2*       pp = g_pref  + b * CHUNKS * N_ST + q;
    #pragma unroll 1
    for (int cb = 0; cb < CHUNKS; cb += 16) {
        float2 cj[16];
        #pragma unroll
        for (int u = 0; u < 16; u++) cj[u] = cp[(cb + u) * N_ST];
        #pragma unroll
        for (int u = 0; u < 16; u++) {
            pp[(cb + u) * N_ST] = pre;
            pre = cmul(lamL, pre);
            pre.x += cj[u].x; pre.y += cj[u].y;
        }
    }
}

// ---------------- kernel 2: HMMA bf16x3 GEMM  y = S_ext @ CD^T ----------------
// smem rows: 64 bf16 data in 72-bf16 (144B) stride -> conflict-free ldmatrix
#define ROWB  144
#define SM_AH 0
#define SM_AL 18432
#define SM_BH 36864
#define SM_BL 55296
#define K2_SMEM 73728

__global__ __launch_bounds__(256, 1) void lru_fix_out(const float* __restrict__ x,
                                                      float* __restrict__ y) {
    extern __shared__ char smem[];
    u32 sb = smem_u32(smem);
    int tid = threadIdx.x;
    int wid = tid >> 5, lane = tid & 31;
    int mw = wid >> 1, nw = wid & 1;      // warp tile: rows mw*32, cols nw*64

    int b  = blockIdx.x >> 5;
    int c4 = blockIdx.x & 31;
    size_t tbase = (size_t)b * T_LEN + c4 * TT2;

    float acc[2][8][4];
    #pragma unroll
    for (int i = 0; i < 2; i++)
        #pragma unroll
        for (int j = 0; j < 8; j++)
            #pragma unroll
            for (int v = 0; v < 4; v++) acc[i][j][v] = 0.f;

    // ldmatrix lane address components
    int arow = mw * 32 + (lane & 7) + ((lane >> 3) & 1) * 8;
    int acol = ((lane >> 4) & 1) * 8;
    u32 aAddrH = sb + SM_AH + arow * ROWB + acol * 2;
    u32 aAddrL = sb + SM_AL + arow * ROWB + acol * 2;
    int brow = nw * 64 + (lane & 7) + (lane >> 4) * 8;
    int bcol = ((lane >> 3) & 1) * 8;
    u32 bAddrH = sb + SM_BH + brow * ROWB + bcol * 2;
    u32 bAddrL = sb + SM_BL + brow * ROWB + bcol * 2;

    for (int kb = 0; kb < 10; kb++) {
        __syncthreads();
        // ---- stage B tiles (copy, restriding 128B rows -> 144B rows) ----
        {
            const float4* sh = (const float4*)(g_CDh + kb * 4096);
            const float4* sl = (const float4*)(g_CDl + kb * 4096);
            #pragma unroll
            for (int i = 0; i < 4; i++) {
                int j4 = tid + i * 256;              // float4 index; d = j4>>3
                int d = j4 >> 3, cc = (j4 & 7) * 16; // byte col
                *(float4*)(smem + SM_BH + d * ROWB + cc) = sh[j4];
                *(float4*)(smem + SM_BL + d * ROWB + cc) = sl[j4];
            }
        }
        // ---- stage A tile: corrected states (or x), bf16 hi/lo ----
        if (kb < 8) {
            #pragma unroll
            for (int i = 0; i < 16; i++) {
                int t = wid * 16 + i;
                float2 s  = g_states[(tbase + t) * N_ST + kb * 32 + lane];
                float2 pr = g_pref[((size_t)b * CHUNKS + c4 * 4 + (t >> 5)) * N_ST + kb * 32 + lane];
                float2 lp = g_lpow[(t & 31) * N_ST + kb * 32 + lane];
                float sre = s.x + lp.x * pr.x - lp.y * pr.y;
                float sim = s.y + lp.x * pr.y + lp.y * pr.x;
                float hr = bfround(sre), hi2 = bfround(sim);
                *(u32*)(smem + SM_AH + t * ROWB + lane * 4) = pkbf(hr, hi2);
                *(u32*)(smem + SM_AL + t * ROWB + lane * 4) = pkbf(sre - hr, sim - hi2);
            }
        } else {
            int kx = (kb - 8) * 64;
            #pragma unroll
            for (int i = 0; i < 16; i++) {
                int t = wid * 16 + i;
                float2 xv = *(const float2*)(x + (tbase + t) * D_INP + kx + lane * 2);
                float h0 = bfround(xv.x), h1 = bfround(xv.y);
                *(u32*)(smem + SM_AH + t * ROWB + lane * 4) = pkbf(h0, h1);
                *(u32*)(smem + SM_AL + t * ROWB + lane * 4) = pkbf(xv.x - h0, xv.y - h1);
            }
        }
        __syncthreads();
        // ---- HMMA: 4 k16-steps x (2 m-tiles x 8 n-tiles) x 3 passes ----
        #pragma unroll
        for (int ks = 0; ks < 4; ks++) {
            u32 off = ks * 32;                        // 16 cols * 2B
            u32 ah[2][4], al[2][4];
            ldmx4(ah[0], aAddrH + off);
            ldmx4(ah[1], aAddrH + 16 * ROWB + off);
            ldmx4(al[0], aAddrL + off);
            ldmx4(al[1], aAddrL + 16 * ROWB + off);
            u32 bh[4][4], bl[4][4];
            #pragma unroll
            for (int ni = 0; ni < 4; ni++) {
                ldmx4(bh[ni], bAddrH + ni * 16 * ROWB + off);
                ldmx4(bl[ni], bAddrL + ni * 16 * ROWB + off);
            }
            #pragma unroll
            for (int mi = 0; mi < 2; mi++)
                #pragma unroll
                for (int ni = 0; ni < 4; ni++) {
                    mma16816(acc[mi][2 * ni],     ah[mi], &bh[ni][0]);
                    mma16816(acc[mi][2 * ni + 1], ah[mi], &bh[ni][2]);
                    mma16816(acc[mi][2 * ni],     al[mi], &bh[ni][0]);
                    mma16816(acc[mi][2 * ni + 1], al[mi], &bh[ni][2]);
                    mma16816(acc[mi][2 * ni],     ah[mi], &bl[ni][0]);
                    mma16816(acc[mi][2 * ni + 1], ah[mi], &bl[ni][2]);
                }
        }
    }

    // ---- epilogue: c frag -> y ----
    #pragma unroll
    for (int mi = 0; mi < 2; mi++) {
        int row = mw * 32 + mi * 16 + (lane >> 2);
        float* yp = y + (tbase + row) * D_OUTP + nw * 64 + (lane & 3) * 2;
        #pragma unroll
        for (int j = 0; j < 8; j++) {
            *(float2*)(yp + j * 8)                = make_float2(acc[mi][j][0], acc[mi][j][1]);
            *(float2*)(yp + j * 8 + 8 * D_OUTP)   = make_float2(acc[mi][j][2], acc[mi][j][3]);
        }
    }
}

// ---------------- launch ----------------
extern "C" void kernel_launch(void* const* d_in, const int* in_sizes, int n_in,
                              void* d_out, int out_size) {
    (void)in_sizes; (void)n_in; (void)out_size;
    const float* x         = (const float*)d_in[0];
    const float* nu_log    = (const float*)d_in[1];
    const float* theta_log = (const float*)d_in[2];
    const float* gamma_log = (const float*)d_in[3];
    const float* B_re      = (const float*)d_in[4];
    const float* B_im      = (const float*)d_in[5];
    const float* C_re      = (const float*)d_in[6];
    const float* C_im      = (const float*)d_in[7];
    const float* Dm        = (const float*)d_in[8];
    float* y = (float*)d_out;

    cudaFuncSetAttribute(lru_bu_scan, cudaFuncAttributeMaxDynamicSharedMemorySize, K1_SMEM);
    cudaFuncSetAttribute(lru_fix_out, cudaFuncAttributeMaxDynamicSharedMemorySize, K2_SMEM);

    lru_prep<<<200, 256>>>(nu_log, theta_log, gamma_log, B_re, B_im, C_re, C_im, Dm);
    lru_bu_scan<<<NBLK1, 512, K1_SMEM>>>(x);
    lru_prefix<<<B_SZ, N_ST>>>();
    lru_fix_out<<<NBLK2, 256, K2_SMEM>>>(x, y);
}

// round 16
// speedup vs baseline: 1.8477x; 1.3530x over previous
#include <cuda_runtime.h>
#include <cuda_bf16.h>
#include <math.h>

#define B_SZ    8
#define T_LEN   4096
#define D_INP   128
#define D_OUTP  128
#define N_ST    256
#define CHUNKS  128                  /* 32-step scan chunks */
#define TT      64                   /* k1 time-tile */
#define NBLK1   (B_SZ * T_LEN / TT)  /* 512 */
#define TT2     128                  /* k2 time-tile */
#define NBLK2   (B_SZ * T_LEN / TT2) /* 256 */

typedef unsigned long long u64;
typedef unsigned int u32;

// ---------------- scratch ----------------
__device__ u32    g_B2h [512 * 64];             // k1 B bf16-hi: [j_real(512)][kpair(64)]
__device__ u32    g_B2l [512 * 64];             // k1 B bf16-lo
__device__ u32    g_CDh [10 * 4096];            // k2 CD bf16-hi: [kb][d][32 u32]
__device__ u32    g_CDl [10 * 4096];            // k2 CD bf16-lo
__device__ float2 g_lpow[32 * N_ST];            // [tm][n] = lam_n^(tm+1)
__device__ float2 g_lam [N_ST];
__device__ float2 g_lamL[N_ST];                 // lambda^32
__device__ float2 g_states[(size_t)B_SZ * T_LEN * N_ST];   // [t][n]
__device__ float2 g_carry[B_SZ * CHUNKS * N_ST];           // [chunk][n]
__device__ float2 g_pref [B_SZ * CHUNKS * N_ST];           // [chunk][n]

// ---------------- helpers ----------------
__device__ __forceinline__ float2 cmul(float2 a, float2 b) {
    return make_float2(a.x * b.x - a.y * b.y, a.x * b.y + a.y * b.x);
}
__device__ __forceinline__ u32 pkbf(float lo, float hi) {    // lo -> low half
    u32 r; asm("cvt.rn.bf16x2.f32 %0, %1, %2;" : "=r"(r) : "f"(hi), "f"(lo)); return r;
}
__device__ __forceinline__ float bfround(float v) {
    return __bfloat162float(__float2bfloat16(v));
}
__device__ __forceinline__ u32 smem_u32(const void* p) {
    u32 a; asm("{ .reg .u64 t; cvta.to.shared.u64 t, %1; cvt.u32.u64 %0, t; }" : "=r"(a) : "l"(p));
    return a;
}
__device__ __forceinline__ void ldmx4(u32* r, u32 addr) {
    asm volatile("ldmatrix.sync.aligned.m8n8.x4.shared.b16 {%0,%1,%2,%3}, [%4];"
                 : "=r"(r[0]), "=r"(r[1]), "=r"(r[2]), "=r"(r[3]) : "r"(addr));
}
__device__ __forceinline__ void mma16816(float* d, const u32* a, const u32* b) {
    asm volatile("mma.sync.aligned.m16n8k16.row.col.f32.bf16.bf16.f32 "
                 "{%0,%1,%2,%3}, {%4,%5,%6,%7}, {%8,%9}, {%0,%1,%2,%3};"
                 : "+f"(d[0]), "+f"(d[1]), "+f"(d[2]), "+f"(d[3])
                 : "r"(a[0]), "r"(a[1]), "r"(a[2]), "r"(a[3]), "r"(b[0]), "r"(b[1]));
}

// ---------------- kernel 0: parameter prep ----------------
__global__ void lru_prep(const float* __restrict__ nu_log,
                         const float* __restrict__ theta_log,
                         const float* __restrict__ gamma_log,
                         const float* __restrict__ B_re, const float* __restrict__ B_im,
                         const float* __restrict__ C_re, const float* __restrict__ C_im,
                         const float* __restrict__ Dm) {
    int idx = blockIdx.x * blockDim.x + threadIdx.x;   // grid covers 51200
    if (idx < N_ST) {
        float la = expf(-expf(nu_log[idx]));
        float ph = expf(theta_log[idx]);
        float2 lam = make_float2(la * cosf(ph), la * sinf(ph));
        g_lam[idx] = lam;
        float2 p = lam;
        #pragma unroll
        for (int i = 0; i < 5; i++) p = cmul(p, p);     // lam^32
        g_lamL[idx] = p;
    }
    if (idx < 512 * 64) {              // k1 B operand: row j = 2n+comp, cols k
        int kp = idx & 63;
        int j  = idx >> 6;
        int n = j >> 1, comp = j & 1;
        float g = expf(gamma_log[n]);
        const float* src = comp ? B_im : B_re;
        float v0 = g * src[n * D_INP + 2 * kp];
        float v1 = g * src[n * D_INP + 2 * kp + 1];
        float h0 = bfround(v0), h1 = bfround(v1);
        g_B2h[idx] = pkbf(h0, h1);
        g_B2l[idx] = pkbf(v0 - h0, v1 - h1);
    }
    if (idx < 10 * 128 * 32) {         // k2 CD bf16 hi/lo tiles [kb][d][kl]
        int kl = idx % 32;
        int d  = (idx / 32) % 128;
        int kb = idx / 4096;
        float v0, v1;
        if (kb < 8) {
            int n = kb * 32 + kl;      // identity layout
            v0 =  C_re[d * N_ST + n];
            v1 = -C_im[d * N_ST + n];
        } else {
            int kk = (kb - 8) * 64 + 2 * kl;
            v0 = Dm[d * D_INP + kk];
            v1 = Dm[d * D_INP + kk + 1];
        }
        float h0 = bfround(v0), h1 = bfround(v1);
        g_CDh[idx] = pkbf(h0, h1);
        g_CDl[idx] = pkbf(v0 - h0, v1 - h1);
    }
    if (idx < 32 * N_ST) {             // lam^(tm+1) table
        int tm = idx >> 8, n = idx & 255;
        float p = (float)(tm + 1);
        float mag = expf(-p * expf(nu_log[n]));
        float ang = p * expf(theta_log[n]);
        g_lpow[idx] = make_float2(mag * cosf(ang), mag * sinf(ang));
    }
}

// ---------------- kernel 1: HMMA Bu = x @ Bc + chunk-local scan ----------------
// smem: xh/xl rows 272B (64 rows) | bh/bl rows 272B (128 rows) | bu rows 560B (64 rows)
#define XROW  272
#define BUROW 560
#define SM_XH 0
#define SM_XL 17408
#define SM_BH 34816
#define SM_BL 69632
#define SM_BU 104448
#define K1_SMEM (104448 + 64 * BUROW)

__global__ __launch_bounds__(256, 1) void lru_bu_scan(const float* __restrict__ x) {
    extern __shared__ char smem[];
    u32 sb = smem_u32(smem);
    int tid = threadIdx.x;
    int wid = tid >> 5, lane = tid & 31;
    int mw = wid >> 1, nw2 = wid & 1;     // warp tile rows mw*16, real-cols nw2*64

    int b  = blockIdx.x >> 6;
    int c2 = blockIdx.x & 63;
    size_t tbase = (size_t)b * T_LEN + c2 * TT;

    // ---- stage x hi/lo ----
    #pragma unroll
    for (int i = 0; i < 16; i++) {
        int idx = tid + i * 256;          // t = idx>>6, kp = idx&63
        int t = idx >> 6, kp = idx & 63;
        float2 xv = *(const float2*)(x + (tbase + t) * D_INP + 2 * kp);
        float h0 = bfround(xv.x), h1 = bfround(xv.y);
        *(u32*)(smem + SM_XH + t * XROW + kp * 4) = pkbf(h0, h1);
        *(u32*)(smem + SM_XL + t * XROW + kp * 4) = pkbf(xv.x - h0, xv.y - h1);
    }

    // ldmatrix lane addresses
    int arow = mw * 16 + (lane & 7) + ((lane >> 3) & 1) * 8;
    int acol = ((lane >> 4) & 1) * 8;
    u32 aAddrH = sb + SM_XH + arow * XROW + acol * 2;
    u32 aAddrL = sb + SM_XL + arow * XROW + acol * 2;
    int brow = nw2 * 64 + (lane & 7) + (lane >> 4) * 8;
    int bcol = ((lane >> 3) & 1) * 8;
    u32 bAddrH = sb + SM_BH + brow * XROW + bcol * 2;
    u32 bAddrL = sb + SM_BL + brow * XROW + bcol * 2;

    int nl = wid * 8 + (lane & 7);        // scan channel within tile
    int sg = lane >> 3;                   // 16-t segment

    for (int nt = 0; nt < 4; nt++) {
        __syncthreads();                  // guard bu/B reuse
        // ---- load B tile (restride 256B -> 272B rows) ----
        {
            const float4* sh = (const float4*)(g_B2h + nt * 8192);
            const float4* sl = (const float4*)(g_B2l + nt * 8192);
            #pragma unroll
            for (int i = 0; i < 8; i++) {
                int j4 = tid + i * 256;   // 2048 float4; row = j4>>4
                int r = j4 >> 4, cc = (j4 & 15) * 16;
                *(float4*)(smem + SM_BH + r * XROW + cc) = sh[j4];
                *(float4*)(smem + SM_BL + r * XROW + cc) = sl[j4];
            }
        }
        __syncthreads();

        // ---- HMMA ----
        float acc[8][4];
        #pragma unroll
        for (int j = 0; j < 8; j++)
            #pragma unroll
            for (int v = 0; v < 4; v++) acc[j][v] = 0.f;

        #pragma unroll
        for (int ks = 0; ks < 8; ks++) {
            u32 off = ks * 32;
            u32 ah[4], al[4];
            ldmx4(ah, aAddrH + off);
            ldmx4(al, aAddrL + off);
            u32 bh[4][4], bl[4][4];
            #pragma unroll
            for (int ni = 0; ni < 4; ni++) {
                ldmx4(bh[ni], bAddrH + ni * 16 * XROW + off);
                ldmx4(bl[ni], bAddrL + ni * 16 * XROW + off);
            }
            #pragma unroll
            for (int ni = 0; ni < 4; ni++) {
                mma16816(acc[2 * ni],     ah, &bh[ni][0]);
                mma16816(acc[2 * ni + 1], ah, &bh[ni][2]);
                mma16816(acc[2 * ni],     al, &bh[ni][0]);
                mma16816(acc[2 * ni + 1], al, &bh[ni][2]);
                mma16816(acc[2 * ni],     ah, &bl[ni][0]);
                mma16816(acc[2 * ni + 1], ah, &bl[ni][2]);
            }
        }
        // ---- c-frags -> bu smem [t][real col] ----
        #pragma unroll
        for (int j = 0; j < 8; j++) {
            int row = mw * 16 + (lane >> 2);
            int col = nw2 * 64 + j * 8 + (lane & 3) * 2;
            *(float2*)(smem + SM_BU + row * BUROW + col * 4)       = make_float2(acc[j][0], acc[j][1]);
            *(float2*)(smem + SM_BU + (row + 8) * BUROW + col * 4) = make_float2(acc[j][2], acc[j][3]);
        }
        __syncthreads();

        // ---- scan: channel n = nt*64 + nl, segment sg (16 t) ----
        {
            int n = nt * 64 + nl;
            float2 lam = g_lam[n];
            float sr[16], si[16];
            float cr = 0.f, ci = 0.f;
            #pragma unroll
            for (int j = 0; j < 16; j++) {
                int t = sg * 16 + j;
                float2 bv = *(const float2*)(smem + SM_BU + t * BUROW + nl * 8);
                float nr = fmaf(lam.x, cr, fmaf(-lam.y, ci, bv.x));
                float ni2 = fmaf(lam.x, ci, fmaf( lam.y, cr, bv.y));
                cr = nr; ci = ni2; sr[j] = nr; si[j] = ni2;
            }
            // carry from even segment to odd segment within each 32-chunk
            float tr = __shfl_up_sync(0xffffffffu, cr, 8);
            float ti = __shfl_up_sync(0xffffffffu, ci, 8);
            float pr = (sg & 1) ? tr : 0.f;
            float pi = (sg & 1) ? ti : 0.f;

            float pwr = lam.x, pwi = lam.y;
            #pragma unroll
            for (int j = 0; j < 16; j++) {
                float rr = fmaf(pwr, pr, fmaf(-pwi, pi, sr[j]));
                float ri = fmaf(pwr, pi, fmaf( pwi, pr, si[j]));
                int t = sg * 16 + j;
                *(float2*)(smem + SM_BU + t * BUROW + nl * 8) = make_float2(rr, ri);
                if (j == 15 && (sg & 1))
                    g_carry[(b * CHUNKS + c2 * 2 + (sg >> 1)) * N_ST + n] = make_float2(rr, ri);
                float npr = fmaf(pwr, lam.x, -pwi * lam.y);
                float npi = fmaf(pwr, lam.y,  pwi * lam.x);
                pwr = npr; pwi = npi;
            }
        }
        __syncthreads();

        // ---- coalesced states write: rows t, cols nt*64..+64 (512B) ----
        {
            int row = tid >> 2, part = tid & 3;
            float2* dst = g_states + (tbase + row) * N_ST + nt * 64 + part * 16;
            #pragma unroll
            for (int v = 0; v < 8; v++) {
                float4 f4 = *(float4*)(smem + SM_BU + row * BUROW + part * 128 + v * 16);
                *(float4*)(dst + v * 2) = f4;
            }
        }
    }
}

// ---------------- kernel 1b: exclusive prefix over chunk carries ----------------
__global__ void lru_prefix() {
    int b = blockIdx.x;            // 8
    int n = threadIdx.x;           // 256
    float2 lamL = g_lamL[n];
    float2 pre = make_float2(0.f, 0.f);
    const float2* cp = g_carry + b * CHUNKS * N_ST + n;
    float2*       pp = g_pref  + b * CHUNKS * N_ST + n;
    #pragma unroll 1
    for (int cb = 0; cb < CHUNKS; cb += 16) {
        float2 cj[16];
        #pragma unroll
        for (int u = 0; u < 16; u++) cj[u] = cp[(cb + u) * N_ST];
        #pragma unroll
        for (int u = 0; u < 16; u++) {
            pp[(cb + u) * N_ST] = pre;
            pre = cmul(lamL, pre);
            pre.x += cj[u].x; pre.y += cj[u].y;
        }
    }
}

// ---------------- kernel 2: HMMA bf16x3 GEMM  y = S_ext @ CD^T ----------------
#define ROWB  144
#define SM_AH 0
#define SM_AL 18432
#define SM_BH2 36864
#define SM_BL2 55296
#define K2_SMEM 73728

__global__ __launch_bounds__(256, 1) void lru_fix_out(const float* __restrict__ x,
                                                      float* __restrict__ y) {
    extern __shared__ char smem[];
    u32 sb = smem_u32(smem);
    int tid = threadIdx.x;
    int wid = tid >> 5, lane = tid & 31;
    int mw = wid >> 1, nw = wid & 1;      // warp tile: rows mw*32, cols nw*64

    int b  = blockIdx.x >> 5;
    int c4 = blockIdx.x & 31;
    size_t tbase = (size_t)b * T_LEN + c4 * TT2;

    float acc[2][8][4];
    #pragma unroll
    for (int i = 0; i < 2; i++)
        #pragma unroll
        for (int j = 0; j < 8; j++)
            #pragma unroll
            for (int v = 0; v < 4; v++) acc[i][j][v] = 0.f;

    int arow = mw * 32 + (lane & 7) + ((lane >> 3) & 1) * 8;
    int acol = ((lane >> 4) & 1) * 8;
    u32 aAddrH = sb + SM_AH + arow * ROWB + acol * 2;
    u32 aAddrL = sb + SM_AL + arow * ROWB + acol * 2;
    int brow = nw * 64 + (lane & 7) + (lane >> 4) * 8;
    int bcol = ((lane >> 3) & 1) * 8;
    u32 bAddrH = sb + SM_BH2 + brow * ROWB + bcol * 2;
    u32 bAddrL = sb + SM_BL2 + brow * ROWB + bcol * 2;

    for (int kb = 0; kb < 10; kb++) {
        __syncthreads();
        // ---- stage B tiles ----
        {
            const float4* sh = (const float4*)(g_CDh + kb * 4096);
            const float4* sl = (const float4*)(g_CDl + kb * 4096);
            #pragma unroll
            for (int i = 0; i < 4; i++) {
                int j4 = tid + i * 256;
                int d = j4 >> 3, cc = (j4 & 7) * 16;
                *(float4*)(smem + SM_BH2 + d * ROWB + cc) = sh[j4];
                *(float4*)(smem + SM_BL2 + d * ROWB + cc) = sl[j4];
            }
        }
        // ---- stage A tile: corrected states (or x), bf16 hi/lo ----
        if (kb < 8) {
            #pragma unroll
            for (int i = 0; i < 16; i++) {
                int t = wid * 16 + i;
                float2 s  = g_states[(tbase + t) * N_ST + kb * 32 + lane];
                float2 pr = g_pref[((size_t)b * CHUNKS + c4 * 4 + (t >> 5)) * N_ST + kb * 32 + lane];
                float2 lp = g_lpow[(t & 31) * N_ST + kb * 32 + lane];
                float sre = s.x + lp.x * pr.x - lp.y * pr.y;
                float sim = s.y + lp.x * pr.y + lp.y * pr.x;
                float hr = bfround(sre), hi2 = bfround(sim);
                *(u32*)(smem + SM_AH + t * ROWB + lane * 4) = pkbf(hr, hi2);
                *(u32*)(smem + SM_AL + t * ROWB + lane * 4) = pkbf(sre - hr, sim - hi2);
            }
        } else {
            int kx = (kb - 8) * 64;
            #pragma unroll
            for (int i = 0; i < 16; i++) {
                int t = wid * 16 + i;
                float2 xv = *(const float2*)(x + (tbase + t) * D_INP + kx + lane * 2);
                float h0 = bfround(xv.x), h1 = bfround(xv.y);
                *(u32*)(smem + SM_AH + t * ROWB + lane * 4) = pkbf(h0, h1);
                *(u32*)(smem + SM_AL + t * ROWB + lane * 4) = pkbf(xv.x - h0, xv.y - h1);
            }
        }
        __syncthreads();
        // ---- HMMA ----
        #pragma unroll
        for (int ks = 0; ks < 4; ks++) {
            u32 off = ks * 32;
            u32 ah[2][4], al[2][4];
            ldmx4(ah[0], aAddrH + off);
            ldmx4(ah[1], aAddrH + 16 * ROWB + off);
            ldmx4(al[0], aAddrL + off);
            ldmx4(al[1], aAddrL + 16 * ROWB + off);
            u32 bh[4][4], bl[4][4];
            #pragma unroll
            for (int ni = 0; ni < 4; ni++) {
                ldmx4(bh[ni], bAddrH + ni * 16 * ROWB + off);
                ldmx4(bl[ni], bAddrL + ni * 16 * ROWB + off);
            }
            #pragma unroll
            for (int mi = 0; mi < 2; mi++)
                #pragma unroll
                for (int ni = 0; ni < 4; ni++) {
                    mma16816(acc[mi][2 * ni],     ah[mi], &bh[ni][0]);
                    mma16816(acc[mi][2 * ni + 1], ah[mi], &bh[ni][2]);
                    mma16816(acc[mi][2 * ni],     al[mi], &bh[ni][0]);
                    mma16816(acc[mi][2 * ni + 1], al[mi], &bh[ni][2]);
                    mma16816(acc[mi][2 * ni],     ah[mi], &bl[ni][0]);
                    mma16816(acc[mi][2 * ni + 1], ah[mi], &bl[ni][2]);
                }
        }
    }

    // ---- epilogue ----
    #pragma unroll
    for (int mi = 0; mi < 2; mi++) {
        int row = mw * 32 + mi * 16 + (lane >> 2);
        float* yp = y + (tbase + row) * D_OUTP + nw * 64 + (lane & 3) * 2;
        #pragma unroll
        for (int j = 0; j < 8; j++) {
            *(float2*)(yp + j * 8)              = make_float2(acc[mi][j][0], acc[mi][j][1]);
            *(float2*)(yp + j * 8 + 8 * D_OUTP) = make_float2(acc[mi][j][2], acc[mi][j][3]);
        }
    }
}

// ---------------- launch ----------------
extern "C" void kernel_launch(void* const* d_in, const int* in_sizes, int n_in,
                              void* d_out, int out_size) {
    (void)in_sizes; (void)n_in; (void)out_size;
    const float* x         = (const float*)d_in[0];
    const float* nu_log    = (const float*)d_in[1];
    const float* theta_log = (const float*)d_in[2];
    const float* gamma_log = (const float*)d_in[3];
    const float* B_re      = (const float*)d_in[4];
    const float* B_im      = (const float*)d_in[5];
    const float* C_re      = (const float*)d_in[6];
    const float* C_im      = (const float*)d_in[7];
    const float* Dm        = (const float*)d_in[8];
    float* y = (float*)d_out;

    cudaFuncSetAttribute(lru_bu_scan, cudaFuncAttributeMaxDynamicSharedMemorySize, K1_SMEM);
    cudaFuncSetAttribute(lru_fix_out, cudaFuncAttributeMaxDynamicSharedMemorySize, K2_SMEM);

    lru_prep<<<200, 256>>>(nu_log, theta_log, gamma_log, B_re, B_im, C_re, C_im, Dm);
    lru_bu_scan<<<NBLK1, 256, K1_SMEM>>>(x);
    lru_prefix<<<B_SZ, N_ST>>>();
    lru_fix_out<<<NBLK2, 256, K2_SMEM>>>(x, y);
}

// round 17
// speedup vs baseline: 1.8678x; 1.0109x over previous
#include <cuda_runtime.h>
#include <cuda_bf16.h>
#include <math.h>

#define B_SZ    8
#define T_LEN   4096
#define D_INP   128
#define D_OUTP  128
#define N_ST    256
#define CHUNKS  128                  /* 32-step scan chunks */
#define TT      64                   /* k1 time-tile */
#define NBLK1   (B_SZ * T_LEN / TT)  /* 512 */
#define TT2     128                  /* k2 time-tile */
#define NBLK2   (B_SZ * T_LEN / TT2) /* 256 */

typedef unsigned long long u64;
typedef unsigned int u32;

// ---------------- scratch ----------------
__device__ u32    g_B2h [512 * 64];             // k1 B bf16-hi: [j_real(512)][kpair(64)]
__device__ u32    g_B2l [512 * 64];             // k1 B bf16-lo
__device__ u32    g_CDh [10 * 4096];            // k2 CD bf16-hi: [kb][d][32 u32]
__device__ u32    g_CDl [10 * 4096];            // k2 CD bf16-lo
__device__ float2 g_lpow[32 * N_ST];            // [tm][n] = lam_n^(tm+1)
__device__ float2 g_lam [N_ST];
__device__ float2 g_lamL[N_ST];                 // lambda^32
__device__ float2 g_states[(size_t)B_SZ * T_LEN * N_ST];   // [t][n]
__device__ float2 g_carry[B_SZ * CHUNKS * N_ST];           // [chunk][n]
__device__ float2 g_pref [B_SZ * CHUNKS * N_ST];           // [chunk][n]

// ---------------- helpers ----------------
__device__ __forceinline__ float2 cmul(float2 a, float2 b) {
    return make_float2(a.x * b.x - a.y * b.y, a.x * b.y + a.y * b.x);
}
__device__ __forceinline__ u32 pkbf(float lo, float hi) {    // lo -> low half
    u32 r; asm("cvt.rn.bf16x2.f32 %0, %1, %2;" : "=r"(r) : "f"(hi), "f"(lo)); return r;
}
__device__ __forceinline__ float bfround(float v) {
    return __bfloat162float(__float2bfloat16(v));
}
__device__ __forceinline__ u32 smem_u32(const void* p) {
    u32 a; asm("{ .reg .u64 t; cvta.to.shared.u64 t, %1; cvt.u32.u64 %0, t; }" : "=r"(a) : "l"(p));
    return a;
}
__device__ __forceinline__ void ldmx4(u32* r, u32 addr) {
    asm volatile("ldmatrix.sync.aligned.m8n8.x4.shared.b16 {%0,%1,%2,%3}, [%4];"
                 : "=r"(r[0]), "=r"(r[1]), "=r"(r[2]), "=r"(r[3]) : "r"(addr));
}
__device__ __forceinline__ void mma16816(float* d, const u32* a, const u32* b) {
    asm volatile("mma.sync.aligned.m16n8k16.row.col.f32.bf16.bf16.f32 "
                 "{%0,%1,%2,%3}, {%4,%5,%6,%7}, {%8,%9}, {%0,%1,%2,%3};"
                 : "+f"(d[0]), "+f"(d[1]), "+f"(d[2]), "+f"(d[3])
                 : "r"(a[0]), "r"(a[1]), "r"(a[2]), "r"(a[3]), "r"(b[0]), "r"(b[1]));
}

// ---------------- kernel 0: parameter prep ----------------
__global__ void lru_prep(const float* __restrict__ nu_log,
                         const float* __restrict__ theta_log,
                         const float* __restrict__ gamma_log,
                         const float* __restrict__ B_re, const float* __restrict__ B_im,
                         const float* __restrict__ C_re, const float* __restrict__ C_im,
                         const float* __restrict__ Dm) {
    int idx = blockIdx.x * blockDim.x + threadIdx.x;   // grid covers 51200
    if (idx < N_ST) {
        float la = expf(-expf(nu_log[idx]));
        float ph = expf(theta_log[idx]);
        float2 lam = make_float2(la * cosf(ph), la * sinf(ph));
        g_lam[idx] = lam;
        float2 p = lam;
        #pragma unroll
        for (int i = 0; i < 5; i++) p = cmul(p, p);     // lam^32
        g_lamL[idx] = p;
    }
    if (idx < 512 * 64) {              // k1 B operand: row j = 2n+comp, cols k
        int kp = idx & 63;
        int j  = idx >> 6;
        int n = j >> 1, comp = j & 1;
        float g = expf(gamma_log[n]);
        const float* src = comp ? B_im : B_re;
        float v0 = g * src[n * D_INP + 2 * kp];
        float v1 = g * src[n * D_INP + 2 * kp + 1];
        float h0 = bfround(v0), h1 = bfround(v1);
        g_B2h[idx] = pkbf(h0, h1);
        g_B2l[idx] = pkbf(v0 - h0, v1 - h1);
    }
    if (idx < 10 * 128 * 32) {         // k2 CD bf16 hi/lo tiles [kb][d][kl]
        int kl = idx % 32;
        int d  = (idx / 32) % 128;
        int kb = idx / 4096;
        float v0, v1;
        if (kb < 8) {
            int n = kb * 32 + kl;      // identity layout
            v0 =  C_re[d * N_ST + n];
            v1 = -C_im[d * N_ST + n];
        } else {
            int kk = (kb - 8) * 64 + 2 * kl;
            v0 = Dm[d * D_INP + kk];
            v1 = Dm[d * D_INP + kk + 1];
        }
        float h0 = bfround(v0), h1 = bfround(v1);
        g_CDh[idx] = pkbf(h0, h1);
        g_CDl[idx] = pkbf(v0 - h0, v1 - h1);
    }
    if (idx < 32 * N_ST) {             // lam^(tm+1) table
        int tm = idx >> 8, n = idx & 255;
        float p = (float)(tm + 1);
        float mag = expf(-p * expf(nu_log[n]));
        float ang = p * expf(theta_log[n]);
        g_lpow[idx] = make_float2(mag * cosf(ang), mag * sinf(ang));
    }
}

// ---------------- kernel 1: HMMA Bu = x @ Bc + chunk-local scan ----------------
// smem: xh/xl rows 272B (64 rows) | bh/bl rows 272B (128 rows) | bu rows 560B (64 rows)
#define XROW  272
#define BUROW 560
#define SM_XH 0
#define SM_XL 17408
#define SM_BH 34816
#define SM_BL 69632
#define SM_BU 104448
#define K1_SMEM (104448 + 64 * BUROW)

__global__ __launch_bounds__(512, 1) void lru_bu_scan(const float* __restrict__ x) {
    extern __shared__ char smem[];
    u32 sb = smem_u32(smem);
    int tid = threadIdx.x;
    int wid = tid >> 5, lane = tid & 31;
    int mw = wid >> 2, nw2 = wid & 3;     // 4x4 warp grid: rows mw*16, real-cols nw2*32

    int b  = blockIdx.x >> 6;
    int c2 = blockIdx.x & 63;
    size_t tbase = (size_t)b * T_LEN + c2 * TT;

    // ---- stage x hi/lo ----
    #pragma unroll
    for (int i = 0; i < 8; i++) {
        int idx = tid + i * 512;          // t = idx>>6, kp = idx&63
        int t = idx >> 6, kp = idx & 63;
        float2 xv = *(const float2*)(x + (tbase + t) * D_INP + 2 * kp);
        float h0 = bfround(xv.x), h1 = bfround(xv.y);
        *(u32*)(smem + SM_XH + t * XROW + kp * 4) = pkbf(h0, h1);
        *(u32*)(smem + SM_XL + t * XROW + kp * 4) = pkbf(xv.x - h0, xv.y - h1);
    }

    // ldmatrix lane addresses
    int arow = mw * 16 + (lane & 7) + ((lane >> 3) & 1) * 8;
    int acol = ((lane >> 4) & 1) * 8;
    u32 aAddrH = sb + SM_XH + arow * XROW + acol * 2;
    u32 aAddrL = sb + SM_XL + arow * XROW + acol * 2;
    int brow = nw2 * 32 + (lane & 7) + (lane >> 4) * 8;
    int bcol = ((lane >> 3) & 1) * 8;
    u32 bAddrH = sb + SM_BH + brow * XROW + bcol * 2;
    u32 bAddrL = sb + SM_BL + brow * XROW + bcol * 2;

    for (int nt = 0; nt < 4; nt++) {
        __syncthreads();                  // guard bu/B reuse
        // ---- load B tile (restride 256B -> 272B rows) ----
        {
            const float4* sh = (const float4*)(g_B2h + nt * 8192);
            const float4* sl = (const float4*)(g_B2l + nt * 8192);
            #pragma unroll
            for (int i = 0; i < 4; i++) {
                int j4 = tid + i * 512;   // 2048 float4; row = j4>>4
                int r = j4 >> 4, cc = (j4 & 15) * 16;
                *(float4*)(smem + SM_BH + r * XROW + cc) = sh[j4];
                *(float4*)(smem + SM_BL + r * XROW + cc) = sl[j4];
            }
        }
        __syncthreads();

        // ---- HMMA: warp tile 16t x 32 real-cols ----
        float acc[4][4];
        #pragma unroll
        for (int j = 0; j < 4; j++)
            #pragma unroll
            for (int v = 0; v < 4; v++) acc[j][v] = 0.f;

        #pragma unroll
        for (int ks = 0; ks < 8; ks++) {
            u32 off = ks * 32;
            u32 ah[4], al[4];
            ldmx4(ah, aAddrH + off);
            ldmx4(al, aAddrL + off);
            u32 bh[2][4], bl[2][4];
            #pragma unroll
            for (int ni = 0; ni < 2; ni++) {
                ldmx4(bh[ni], bAddrH + ni * 16 * XROW + off);
                ldmx4(bl[ni], bAddrL + ni * 16 * XROW + off);
            }
            #pragma unroll
            for (int ni = 0; ni < 2; ni++) {
                mma16816(acc[2 * ni],     ah, &bh[ni][0]);
                mma16816(acc[2 * ni + 1], ah, &bh[ni][2]);
                mma16816(acc[2 * ni],     al, &bh[ni][0]);
                mma16816(acc[2 * ni + 1], al, &bh[ni][2]);
                mma16816(acc[2 * ni],     ah, &bl[ni][0]);
                mma16816(acc[2 * ni + 1], ah, &bl[ni][2]);
            }
        }
        // ---- c-frags -> bu smem [t][real col] ----
        #pragma unroll
        for (int j = 0; j < 4; j++) {
            int row = mw * 16 + (lane >> 2);
            int col = nw2 * 32 + j * 8 + (lane & 3) * 2;
            *(float2*)(smem + SM_BU + row * BUROW + col * 4)       = make_float2(acc[j][0], acc[j][1]);
            *(float2*)(smem + SM_BU + (row + 8) * BUROW + col * 4) = make_float2(acc[j][2], acc[j][3]);
        }
        __syncthreads();

        // ---- scan (first 256 threads): channel n = nt*64 + nl, segment sg (16 t) ----
        if (tid < 256) {
            int wid8 = tid >> 5;
            int nl = wid8 * 8 + (lane & 7);
            int sg = lane >> 3;
            int n = nt * 64 + nl;
            float2 lam = g_lam[n];
            float sr[16], si[16];
            float cr = 0.f, ci = 0.f;
            #pragma unroll
            for (int j = 0; j < 16; j++) {
                int t = sg * 16 + j;
                float2 bv = *(const float2*)(smem + SM_BU + t * BUROW + nl * 8);
                float nr = fmaf(lam.x, cr, fmaf(-lam.y, ci, bv.x));
                float ni2 = fmaf(lam.x, ci, fmaf( lam.y, cr, bv.y));
                cr = nr; ci = ni2; sr[j] = nr; si[j] = ni2;
            }
            // carry from even segment to odd segment within each 32-chunk
            float tr = __shfl_up_sync(0xffffffffu, cr, 8);
            float ti = __shfl_up_sync(0xffffffffu, ci, 8);
            float pr = (sg & 1) ? tr : 0.f;
            float pi = (sg & 1) ? ti : 0.f;

            float pwr = lam.x, pwi = lam.y;
            #pragma unroll
            for (int j = 0; j < 16; j++) {
                float rr = fmaf(pwr, pr, fmaf(-pwi, pi, sr[j]));
                float ri = fmaf(pwr, pi, fmaf( pwi, pr, si[j]));
                int t = sg * 16 + j;
                *(float2*)(smem + SM_BU + t * BUROW + nl * 8) = make_float2(rr, ri);
                if (j == 15 && (sg & 1))
                    g_carry[(b * CHUNKS + c2 * 2 + (sg >> 1)) * N_ST + n] = make_float2(rr, ri);
                float npr = fmaf(pwr, lam.x, -pwi * lam.y);
                float npi = fmaf(pwr, lam.y,  pwi * lam.x);
                pwr = npr; pwi = npi;
            }
        }
        __syncthreads();

        // ---- coalesced states write: rows t, cols nt*64..+64 (512B/row) ----
        {
            int row = tid >> 3, part = tid & 7;
            float2* dst = g_states + (tbase + row) * N_ST + nt * 64 + part * 8;
            #pragma unroll
            for (int v = 0; v < 4; v++) {
                float4 f4 = *(float4*)(smem + SM_BU + row * BUROW + part * 64 + v * 16);
                *(float4*)((float*)dst + v * 4) = f4;
            }
        }
    }
}

// ---------------- kernel 1b: exclusive prefix over chunk carries ----------------
__global__ void lru_prefix() {
    int b = blockIdx.x;            // 8
    int n = threadIdx.x;           // 256
    float2 lamL = g_lamL[n];
    float2 pre = make_float2(0.f, 0.f);
    const float2* cp = g_carry + b * CHUNKS * N_ST + n;
    float2*       pp = g_pref  + b * CHUNKS * N_ST + n;
    #pragma unroll 1
    for (int cb = 0; cb < CHUNKS; cb += 16) {
        float2 cj[16];
        #pragma unroll
        for (int u = 0; u < 16; u++) cj[u] = cp[(cb + u) * N_ST];
        #pragma unroll
        for (int u = 0; u < 16; u++) {
            pp[(cb + u) * N_ST] = pre;
            pre = cmul(lamL, pre);
            pre.x += cj[u].x; pre.y += cj[u].y;
        }
    }
}

// ---------------- kernel 2: HMMA bf16x3 GEMM  y = S_ext @ CD^T ----------------
#define ROWB  144
#define SM_AH 0
#define SM_AL 18432
#define SM_BH2 36864
#define SM_BL2 55296
#define K2_SMEM 73728

__global__ __launch_bounds__(512, 1) void lru_fix_out(const float* __restrict__ x,
                                                      float* __restrict__ y) {
    extern __shared__ char smem[];
    u32 sb = smem_u32(smem);
    int tid = threadIdx.x;
    int wid = tid >> 5, lane = tid & 31;
    int mw = wid >> 1, nw = wid & 1;      // 8x2 warp grid: rows mw*16, cols nw*64

    int b  = blockIdx.x >> 5;
    int c4 = blockIdx.x & 31;
    size_t tbase = (size_t)b * T_LEN + c4 * TT2;

    float acc[8][4];
    #pragma unroll
    for (int j = 0; j < 8; j++)
        #pragma unroll
        for (int v = 0; v < 4; v++) acc[j][v] = 0.f;

    int arow = mw * 16 + (lane & 7) + ((lane >> 3) & 1) * 8;
    int acol = ((lane >> 4) & 1) * 8;
    u32 aAddrH = sb + SM_AH + arow * ROWB + acol * 2;
    u32 aAddrL = sb + SM_AL + arow * ROWB + acol * 2;
    int brow = nw * 64 + (lane & 7) + (lane >> 4) * 8;
    int bcol = ((lane >> 3) & 1) * 8;
    u32 bAddrH = sb + SM_BH2 + brow * ROWB + bcol * 2;
    u32 bAddrL = sb + SM_BL2 + brow * ROWB + bcol * 2;

    for (int kb = 0; kb < 10; kb++) {
        __syncthreads();
        // ---- stage B tiles ----
        {
            const float4* sh = (const float4*)(g_CDh + kb * 4096);
            const float4* sl = (const float4*)(g_CDl + kb * 4096);
            #pragma unroll
            for (int i = 0; i < 2; i++) {
                int j4 = tid + i * 512;
                int d = j4 >> 3, cc = (j4 & 7) * 16;
                *(float4*)(smem + SM_BH2 + d * ROWB + cc) = sh[j4];
                *(float4*)(smem + SM_BL2 + d * ROWB + cc) = sl[j4];
            }
        }
        // ---- stage A tile: corrected states (or x), bf16 hi/lo; warp stages 8 rows ----
        if (kb < 8) {
            #pragma unroll
            for (int i = 0; i < 8; i++) {
                int t = wid * 8 + i;
                float2 s  = g_states[(tbase + t) * N_ST + kb * 32 + lane];
                float2 pr = g_pref[((size_t)b * CHUNKS + c4 * 4 + (t >> 5)) * N_ST + kb * 32 + lane];
                float2 lp = g_lpow[(t & 31) * N_ST + kb * 32 + lane];
                float sre = s.x + lp.x * pr.x - lp.y * pr.y;
                float sim = s.y + lp.x * pr.y + lp.y * pr.x;
                float hr = bfround(sre), hi2 = bfround(sim);
                *(u32*)(smem + SM_AH + t * ROWB + lane * 4) = pkbf(hr, hi2);
                *(u32*)(smem + SM_AL + t * ROWB + lane * 4) = pkbf(sre - hr, sim - hi2);
            }
        } else {
            int kx = (kb - 8) * 64;
            #pragma unroll
            for (int i = 0; i < 8; i++) {
                int t = wid * 8 + i;
                float2 xv = *(const float2*)(x + (tbase + t) * D_INP + kx + lane * 2);
                float h0 = bfround(xv.x), h1 = bfround(xv.y);
                *(u32*)(smem + SM_AH + t * ROWB + lane * 4) = pkbf(h0, h1);
                *(u32*)(smem + SM_AL + t * ROWB + lane * 4) = pkbf(xv.x - h0, xv.y - h1);
            }
        }
        __syncthreads();
        // ---- HMMA: warp tile 16t x 64d ----
        #pragma unroll
        for (int ks = 0; ks < 4; ks++) {
            u32 off = ks * 32;
            u32 ah[4], al[4];
            ldmx4(ah, aAddrH + off);
            ldmx4(al, aAddrL + off);
            u32 bh[4][4], bl[4][4];
            #pragma unroll
            for (int ni = 0; ni < 4; ni++) {
                ldmx4(bh[ni], bAddrH + ni * 16 * ROWB + off);
                ldmx4(bl[ni], bAddrL + ni * 16 * ROWB + off);
            }
            #pragma unroll
            for (int ni = 0; ni < 4; ni++) {
                mma16816(acc[2 * ni],     ah, &bh[ni][0]);
                mma16816(acc[2 * ni + 1], ah, &bh[ni][2]);
                mma16816(acc[2 * ni],     al, &bh[ni][0]);
                mma16816(acc[2 * ni + 1], al, &bh[ni][2]);
                mma16816(acc[2 * ni],     ah, &bl[ni][0]);
                mma16816(acc[2 * ni + 1], ah, &bl[ni][2]);
            }
        }
    }

    // ---- epilogue ----
    {
        int row = mw * 16 + (lane >> 2);
        float* yp = y + (tbase + row) * D_OUTP + nw * 64 + (lane & 3) * 2;
        #pragma unroll
        for (int j = 0; j < 8; j++) {
            *(float2*)(yp + j * 8)              = make_float2(acc[j][0], acc[j][1]);
            *(float2*)(yp + j * 8 + 8 * D_OUTP) = make_float2(acc[j][2], acc[j][3]);
        }
    }
}

// ---------------- launch ----------------
extern "C" void kernel_launch(void* const* d_in, const int* in_sizes, int n_in,
                              void* d_out, int out_size) {
    (void)in_sizes; (void)n_in; (void)out_size;
    const float* x         = (const float*)d_in[0];
    const float* nu_log    = (const float*)d_in[1];
    const float* theta_log = (const float*)d_in[2];
    const float* gamma_log = (const float*)d_in[3];
    const float* B_re      = (const float*)d_in[4];
    const float* B_im      = (const float*)d_in[5];
    const float* C_re      = (const float*)d_in[6];
    const float* C_im      = (const float*)d_in[7];
    const float* Dm        = (const float*)d_in[8];
    float* y = (float*)d_out;

    cudaFuncSetAttribute(lru_bu_scan, cudaFuncAttributeMaxDynamicSharedMemorySize, K1_SMEM);
    cudaFuncSetAttribute(lru_fix_out, cudaFuncAttributeMaxDynamicSharedMemorySize, K2_SMEM);

    lru_prep<<<200, 256>>>(nu_log, theta_log, gamma_log, B_re, B_im, C_re, C_im, Dm);
    lru_bu_scan<<<NBLK1, 512, K1_SMEM>>>(x);
    lru_prefix<<<B_SZ, N_ST>>>();
    lru_fix_out<<<NBLK2, 512, K2_SMEM>>>(x, y);
}